// round 11
// baseline (speedup 1.0000x reference)
#include <cuda_runtime.h>
#include <cuda_fp16.h>
#include <cuda_bf16.h>

#define N_NODES 100000
#define N_EDGES 1600000
#define TOT (N_EDGES + N_NODES)
#define NB_SCAN ((N_NODES + 1023) / 1024)   // 98

// ---------------- scratch -----------------------------------------------------
__device__ int    g_deg[N_NODES];
__device__ int    g_incl[N_NODES];
__device__ int    g_bsum[128];
__device__ int    g_rowptr[N_NODES + 1];
__device__ int    g_cursor[N_NODES];
__device__ int2   g_cw[TOT];             // {src*64, __float_as_int(dinv[src])}  (layer 0)
__device__ int    g_col[TOT];            // src*64 only                          (layers 1,2)
__device__ float  g_dinv[N_NODES];
__device__ int    g_is64;

__device__ __align__(256) __half g_M[N_NODES * 64];   // fp16 message buffer
__device__ float g_XT[N_NODES * 64];                  // x_temp residual (fp32)
__device__ float g_h1[N_NODES * 64];                  // hidden (fp32)

// ---------------- helpers ------------------------------------------------------
__device__ __forceinline__ int load_idx(const void* ei, int pos) {
    if (g_is64) return (int)((const long long*)ei)[pos];
    return ((const int*)ei)[pos];
}

__global__ void k_init(const void* ei) {
    int i = blockIdx.x * blockDim.x + threadIdx.x;
    if (i < N_NODES) g_deg[i] = 1;
    if (i == 0) {
        const long long* p = (const long long*)ei;
        int ok64 = 1;
        #pragma unroll
        for (int j = 0; j < 16; j++) {
            long long v = p[j];
            if (v < 0 || v >= N_NODES) ok64 = 0;
        }
        g_is64 = ok64;
    }
}

__global__ void k_count(const void* ei) {
    int t = blockIdx.x * blockDim.x + threadIdx.x;
    if (t < N_EDGES) atomicAdd(&g_deg[load_idx(ei, N_EDGES + t)], 1);
}

__global__ void k_scan1() {
    __shared__ int s[1024];
    int tid = threadIdx.x;
    int i = blockIdx.x * 1024 + tid;
    int v = (i < N_NODES) ? g_deg[i] : 0;
    s[tid] = v;
    __syncthreads();
    #pragma unroll
    for (int off = 1; off < 1024; off <<= 1) {
        int t = (tid >= off) ? s[tid - off] : 0;
        __syncthreads();
        s[tid] += t;
        __syncthreads();
    }
    if (i < N_NODES) g_incl[i] = s[tid];
    if (tid == 1023) g_bsum[blockIdx.x] = s[1023];
}

__global__ void k_scan2f() {
    __shared__ int sb[128];
    int tid = threadIdx.x;
    if (tid < 128) sb[tid] = (tid < NB_SCAN) ? g_bsum[tid] : 0;
    __syncthreads();
    int boff = 0;
    for (int j = 0; j < (int)blockIdx.x; j++) boff += sb[j];
    int i = blockIdx.x * 1024 + tid;
    if (i < N_NODES) {
        int rp = g_incl[i] - g_deg[i] + boff;
        g_rowptr[i] = rp;
        g_cursor[i] = rp;
        g_dinv[i]   = rsqrtf((float)g_deg[i]);
    }
    if (i == 0) g_rowptr[N_NODES] = TOT;
}

__global__ void k_fill(const void* ei) {
    int t = blockIdx.x * blockDim.x + threadIdx.x;
    if (t < N_EDGES) {
        int s = load_idx(ei, t);
        int d = load_idx(ei, N_EDGES + t);
        int pos = atomicAdd(&g_cursor[d], 1);
        g_cw[pos]  = make_int2(s * 64, __float_as_int(g_dinv[s]));
        g_col[pos] = s * 64;
    } else if (t < TOT) {
        int i = t - N_EDGES;
        int pos = atomicAdd(&g_cursor[i], 1);
        g_cw[pos]  = make_int2(i * 64, __float_as_int(g_dinv[i]));
        g_col[pos] = i * 64;
    }
}

// ---------------- tiled GEMM: M16 = [dinv *] (X @ W),  fp16 out ---------------
template <int K, bool SCALE>
__global__ void __launch_bounds__(256) k_gemm(const float* __restrict__ X,
                                              const float* __restrict__ W,
                                              __half* __restrict__ M) {
    __shared__ float As[32][132];
    __shared__ float Bs[32][64];
    int tid = threadIdx.x;
    int block_row = blockIdx.x * 128;
    int txc = tid & 7;
    int tyr = tid >> 3;

    int lrow = tid >> 1;
    int kh   = (tid & 1) * 16;
    int lkB  = tid >> 3;
    int lcB  = (tid & 7) * 8;

    float acc[4][8];
    #pragma unroll
    for (int i = 0; i < 4; i++)
        #pragma unroll
        for (int j = 0; j < 8; j++) acc[i][j] = 0.f;

    for (int k0 = 0; k0 < K; k0 += 32) {
        int grow = block_row + lrow;
        #pragma unroll
        for (int j = 0; j < 4; j++) {
            int ko = kh + j * 4;
            float4 v = make_float4(0.f, 0.f, 0.f, 0.f);
            if (grow < N_NODES) v = *(const float4*)&X[(size_t)grow * K + k0 + ko];
            As[ko + 0][lrow] = v.x;
            As[ko + 1][lrow] = v.y;
            As[ko + 2][lrow] = v.z;
            As[ko + 3][lrow] = v.w;
        }
        *(float4*)&Bs[lkB][lcB]     = *(const float4*)&W[(size_t)(k0 + lkB) * 64 + lcB];
        *(float4*)&Bs[lkB][lcB + 4] = *(const float4*)&W[(size_t)(k0 + lkB) * 64 + lcB + 4];
        __syncthreads();

        #pragma unroll 8
        for (int kk = 0; kk < 32; kk++) {
            float4 a  = *(const float4*)&As[kk][tyr * 4];
            float4 b0 = *(const float4*)&Bs[kk][txc * 8];
            float4 b1 = *(const float4*)&Bs[kk][txc * 8 + 4];
            float av[4] = {a.x, a.y, a.z, a.w};
            float bv[8] = {b0.x, b0.y, b0.z, b0.w, b1.x, b1.y, b1.z, b1.w};
            #pragma unroll
            for (int i = 0; i < 4; i++)
                #pragma unroll
                for (int j = 0; j < 8; j++)
                    acc[i][j] = fmaf(av[i], bv[j], acc[i][j]);
        }
        __syncthreads();
    }

    #pragma unroll
    for (int i = 0; i < 4; i++) {
        int gr = block_row + tyr * 4 + i;
        if (gr < N_NODES) {
            float di = SCALE ? g_dinv[gr] : 1.f;
            __half2 h[4];
            #pragma unroll
            for (int j = 0; j < 4; j++)
                h[j] = __floats2half2_rn(acc[i][2 * j] * di, acc[i][2 * j + 1] * di);
            uint4 pack;
            pack.x = *(unsigned*)&h[0];
            pack.y = *(unsigned*)&h[1];
            pack.z = *(unsigned*)&h[2];
            pack.w = *(unsigned*)&h[3];
            *(uint4*)&M[(size_t)gr * 64 + txc * 8] = pack;
        }
    }
}

// ---------------- persistent half-warp fp16 aggregate -------------------------
// grid-stride over rows (one wave of blocks); half-warp per edge pair,
// lane loads uint2 = 4 halves. No per-row block launch churn.
template <bool WEIGHTED, bool RELU, bool ADDRES>
__global__ void __launch_bounds__(512) k_agg(const __half* __restrict__ M,
                                             const float* __restrict__ bias,
                                             const float* __restrict__ res,
                                             float* __restrict__ outp) {
    int lane = threadIdx.x & 31;
    int hid  = lane >> 4;
    int hl4  = (lane & 15) * 4;
    int w0   = (blockIdx.x * 512 + threadIdx.x) >> 5;
    int nw   = (gridDim.x * 512) >> 5;

    for (int row = w0; row < N_NODES; row += nw) {
        int s  = g_rowptr[row];
        int en = g_rowptr[row + 1];
        float a0 = 0.f, a1 = 0.f, a2 = 0.f, a3 = 0.f;
        int e = s;

        #pragma unroll 1
        for (; e + 8 <= en; e += 8) {
            #pragma unroll
            for (int j = 0; j < 4; j++) {
                int   c;
                float w;
                if (WEIGHTED) {
                    int2 cw = g_cw[e + 2 * j + hid];
                    c = cw.x;
                    w = __int_as_float(cw.y);
                } else {
                    c = g_col[e + 2 * j + hid];
                    w = 1.f;
                }
                uint2 hv = *(const uint2*)&M[c + hl4];
                float2 lo = __half22float2(*(__half2*)&hv.x);
                float2 hi = __half22float2(*(__half2*)&hv.y);
                if (WEIGHTED) {
                    a0 = fmaf(lo.x, w, a0); a1 = fmaf(lo.y, w, a1);
                    a2 = fmaf(hi.x, w, a2); a3 = fmaf(hi.y, w, a3);
                } else {
                    a0 += lo.x; a1 += lo.y; a2 += hi.x; a3 += hi.y;
                }
            }
        }
        for (; e + 2 <= en; e += 2) {
            int   c;
            float w;
            if (WEIGHTED) {
                int2 cw = g_cw[e + hid];
                c = cw.x;
                w = __int_as_float(cw.y);
            } else {
                c = g_col[e + hid];
                w = 1.f;
            }
            uint2 hv = *(const uint2*)&M[c + hl4];
            float2 lo = __half22float2(*(__half2*)&hv.x);
            float2 hi = __half22float2(*(__half2*)&hv.y);
            a0 = fmaf(lo.x, w, a0); a1 = fmaf(lo.y, w, a1);
            a2 = fmaf(hi.x, w, a2); a3 = fmaf(hi.y, w, a3);
        }
        if (e < en && hid == 0) {
            int   c;
            float w;
            if (WEIGHTED) {
                int2 cw = g_cw[e];
                c = cw.x;
                w = __int_as_float(cw.y);
            } else {
                c = g_col[e];
                w = 1.f;
            }
            uint2 hv = *(const uint2*)&M[c + hl4];
            float2 lo = __half22float2(*(__half2*)&hv.x);
            float2 hi = __half22float2(*(__half2*)&hv.y);
            a0 = fmaf(lo.x, w, a0); a1 = fmaf(lo.y, w, a1);
            a2 = fmaf(hi.x, w, a2); a3 = fmaf(hi.y, w, a3);
        }
        // combine half-warps
        a0 += __shfl_xor_sync(0xffffffffu, a0, 16);
        a1 += __shfl_xor_sync(0xffffffffu, a1, 16);
        a2 += __shfl_xor_sync(0xffffffffu, a2, 16);
        a3 += __shfl_xor_sync(0xffffffffu, a3, 16);

        if (hid == 0) {
            float di = g_dinv[row];
            float4 b = *(const float4*)&bias[hl4];
            float o0 = fmaf(a0, di, b.x);
            float o1 = fmaf(a1, di, b.y);
            float o2 = fmaf(a2, di, b.z);
            float o3 = fmaf(a3, di, b.w);
            if (RELU) {
                o0 = fmaxf(o0, 0.f); o1 = fmaxf(o1, 0.f);
                o2 = fmaxf(o2, 0.f); o3 = fmaxf(o3, 0.f);
            }
            if (ADDRES) {
                float4 r = *(const float4*)&res[(size_t)row * 64 + hl4];
                o0 += r.x; o1 += r.y; o2 += r.z; o3 += r.w;
            }
            *(float4*)&outp[(size_t)row * 64 + hl4] = make_float4(o0, o1, o2, o3);
        }
    }
}

// ---------------- launch --------------------------------------------------------
extern "C" void kernel_launch(void* const* d_in, const int* in_sizes, int n_in,
                              void* d_out, int out_size) {
    const float* x  = (const float*)d_in[0];
    const void*  ei = d_in[1];
    const float* W0 = (const float*)d_in[2];
    const float* b0 = (const float*)d_in[3];
    const float* Ws = (const float*)d_in[4];
    const float* bs = (const float*)d_in[5];
    float* out = (float*)d_out;

    const float* Ws0 = Ws;
    const float* Ws1 = Ws + 64 * 64;
    const float* bs0 = bs;
    const float* bs1 = bs + 64;

    __half* M = nullptr;
    float *XT = nullptr, *H1 = nullptr;
    cudaGetSymbolAddress((void**)&M,  g_M);
    cudaGetSymbolAddress((void**)&XT, g_XT);
    cudaGetSymbolAddress((void**)&H1, g_h1);

    static cudaStream_t s2 = nullptr;
    static cudaEvent_t evF = nullptr, evG = nullptr;
    if (s2 == nullptr) {
        cudaStreamCreateWithFlags(&s2, cudaStreamNonBlocking);
        cudaEventCreateWithFlags(&evF, cudaEventDisableTiming);
        cudaEventCreateWithFlags(&evG, cudaEventDisableTiming);
    }

    const int GEMM_BLOCKS = (N_NODES + 127) / 128;   // 782
    const int AGG_BLOCKS  = 592;                     // 4 blocks/SM, persistent

    // ---- fork: gemm0 (independent of graph build) on side stream ----
    cudaEventRecord(evF, 0);
    cudaStreamWaitEvent(s2, evF, 0);
    k_gemm<128, false><<<GEMM_BLOCKS, 256, 0, s2>>>(x, W0, M);  // M = fp16(x@W0)
    cudaEventRecord(evG, s2);

    // ---- CSR build on default stream (concurrent with gemm0) ----
    k_init<<<(N_NODES + 255) / 256, 256>>>(ei);
    k_count<<<(N_EDGES + 511) / 512, 512>>>(ei);
    k_scan1<<<NB_SCAN, 1024>>>();
    k_scan2f<<<NB_SCAN, 1024>>>();
    k_fill<<<(TOT + 511) / 512, 512>>>(ei);

    // ---- join, then the serial conv chain ----
    cudaStreamWaitEvent(0, evG, 0);
    // layer 0: XT = agg_w(M) + b0   (per-edge dinv[src] weights)
    k_agg<true, false, false><<<AGG_BLOCKS, 512>>>(M, b0, nullptr, XT);
    // layer 1: M = fp16(dinv*(XT@Ws0)); h1 = relu(agg(M)+bs0)
    k_gemm<64, true><<<GEMM_BLOCKS, 256>>>(XT, Ws0, M);
    k_agg<false, true, false><<<AGG_BLOCKS, 512>>>(M, bs0, nullptr, H1);
    // layer 2: M = fp16(dinv*(h1@Ws1)); out = relu(agg(M)+bs1) + XT
    k_gemm<64, true><<<GEMM_BLOCKS, 256>>>(H1, Ws1, M);
    k_agg<false, true, true><<<AGG_BLOCKS, 512>>>(M, bs1, XT, out);
}

// round 12
// speedup vs baseline: 1.0341x; 1.0341x over previous
#include <cuda_runtime.h>
#include <cuda_fp16.h>
#include <cuda_bf16.h>

#define N_NODES 100000
#define N_EDGES 1600000
#define TOT (N_EDGES + N_NODES)
#define NB_SCAN ((N_NODES + 1023) / 1024)   // 98

// ---------------- scratch (zero-initialized at module load) -------------------
__device__ int    g_deg[N_NODES];        // raw edge counts; re-zeroed by k_fill
__device__ int    g_incl[N_NODES];
__device__ int    g_bsum[128];
__device__ int    g_rowptr[N_NODES + 1];
__device__ int    g_cursor[N_NODES];
__device__ int2   g_cw[TOT];             // {src*64, __float_as_int(dinv[src])}
__device__ float  g_dinv[N_NODES];

__device__ __align__(256) __half g_M[N_NODES * 64];   // fp16 message buffer
__device__ float g_XT[N_NODES * 64];                  // x_temp residual (fp32)
__device__ float g_h1[N_NODES * 64];                  // hidden (fp32)

// ---------------- helpers ------------------------------------------------------
// int64 edge_index may be silently stored as int32; detect per-thread (broadcast
// loads, uniform branch, cached — effectively free).
__device__ __forceinline__ bool detect64(const void* ei) {
    const long long* p = (const long long*)ei;
    bool ok64 = true;
    #pragma unroll
    for (int j = 0; j < 16; j++) {
        long long v = p[j];
        if (v < 0 || v >= N_NODES) ok64 = false;
    }
    return ok64;
}

__device__ __forceinline__ int load_idx(const void* ei, int pos, bool is64) {
    if (is64) return (int)((const long long*)ei)[pos];
    return ((const int*)ei)[pos];
}

__global__ void k_count(const void* ei) {
    bool is64 = detect64(ei);
    int t = blockIdx.x * blockDim.x + threadIdx.x;
    if (t < N_EDGES) atomicAdd(&g_deg[load_idx(ei, N_EDGES + t, is64)], 1);
}

__global__ void k_scan1() {
    __shared__ int s[1024];
    int tid = threadIdx.x;
    int i = blockIdx.x * 1024 + tid;
    int v = (i < N_NODES) ? (g_deg[i] + 1) : 0;   // +1 = self loop
    s[tid] = v;
    __syncthreads();
    #pragma unroll
    for (int off = 1; off < 1024; off <<= 1) {
        int t = (tid >= off) ? s[tid - off] : 0;
        __syncthreads();
        s[tid] += t;
        __syncthreads();
    }
    if (i < N_NODES) g_incl[i] = s[tid];
    if (tid == 1023) g_bsum[blockIdx.x] = s[1023];
}

__global__ void k_scan2f() {
    __shared__ int sb[128];
    int tid = threadIdx.x;
    if (tid < 128) sb[tid] = (tid < NB_SCAN) ? g_bsum[tid] : 0;
    __syncthreads();
    int boff = 0;
    for (int j = 0; j < (int)blockIdx.x; j++) boff += sb[j];
    int i = blockIdx.x * 1024 + tid;
    if (i < N_NODES) {
        int d  = g_deg[i] + 1;                    // incl self loop
        int rp = g_incl[i] - d + boff;
        g_rowptr[i] = rp;
        g_cursor[i] = rp;
        g_dinv[i]   = rsqrtf((float)d);
    }
    if (i == 0) g_rowptr[N_NODES] = TOT;
}

__global__ void k_fill(const void* ei) {
    bool is64 = detect64(ei);
    int t = blockIdx.x * blockDim.x + threadIdx.x;
    if (t < N_EDGES) {
        int s = load_idx(ei, t, is64);
        int d = load_idx(ei, N_EDGES + t, is64);
        int pos = atomicAdd(&g_cursor[d], 1);
        g_cw[pos] = make_int2(s * 64, __float_as_int(g_dinv[s]));
    } else if (t < TOT) {
        int i = t - N_EDGES;
        int pos = atomicAdd(&g_cursor[i], 1);
        g_cw[pos] = make_int2(i * 64, __float_as_int(g_dinv[i]));
    }
    // restore the zero-state invariant for the next replay (no kernel reads
    // g_deg after k_scan2f in this run; first-ever run sees the load-time zeros)
    if (t < N_NODES) g_deg[t] = 0;
}

// ---------------- tiled GEMM: M16 = [dinv *] (X @ W),  fp16 out ---------------
template <int K, bool SCALE>
__global__ void __launch_bounds__(256) k_gemm(const float* __restrict__ X,
                                              const float* __restrict__ W,
                                              __half* __restrict__ M) {
    __shared__ float As[32][132];
    __shared__ float Bs[32][64];
    int tid = threadIdx.x;
    int block_row = blockIdx.x * 128;
    int txc = tid & 7;
    int tyr = tid >> 3;

    int lrow = tid >> 1;
    int kh   = (tid & 1) * 16;
    int lkB  = tid >> 3;
    int lcB  = (tid & 7) * 8;

    float acc[4][8];
    #pragma unroll
    for (int i = 0; i < 4; i++)
        #pragma unroll
        for (int j = 0; j < 8; j++) acc[i][j] = 0.f;

    for (int k0 = 0; k0 < K; k0 += 32) {
        int grow = block_row + lrow;
        #pragma unroll
        for (int j = 0; j < 4; j++) {
            int ko = kh + j * 4;
            float4 v = make_float4(0.f, 0.f, 0.f, 0.f);
            if (grow < N_NODES) v = *(const float4*)&X[(size_t)grow * K + k0 + ko];
            As[ko + 0][lrow] = v.x;
            As[ko + 1][lrow] = v.y;
            As[ko + 2][lrow] = v.z;
            As[ko + 3][lrow] = v.w;
        }
        *(float4*)&Bs[lkB][lcB]     = *(const float4*)&W[(size_t)(k0 + lkB) * 64 + lcB];
        *(float4*)&Bs[lkB][lcB + 4] = *(const float4*)&W[(size_t)(k0 + lkB) * 64 + lcB + 4];
        __syncthreads();

        #pragma unroll 8
        for (int kk = 0; kk < 32; kk++) {
            float4 a  = *(const float4*)&As[kk][tyr * 4];
            float4 b0 = *(const float4*)&Bs[kk][txc * 8];
            float4 b1 = *(const float4*)&Bs[kk][txc * 8 + 4];
            float av[4] = {a.x, a.y, a.z, a.w};
            float bv[8] = {b0.x, b0.y, b0.z, b0.w, b1.x, b1.y, b1.z, b1.w};
            #pragma unroll
            for (int i = 0; i < 4; i++)
                #pragma unroll
                for (int j = 0; j < 8; j++)
                    acc[i][j] = fmaf(av[i], bv[j], acc[i][j]);
        }
        __syncthreads();
    }

    #pragma unroll
    for (int i = 0; i < 4; i++) {
        int gr = block_row + tyr * 4 + i;
        if (gr < N_NODES) {
            float di = SCALE ? g_dinv[gr] : 1.f;
            __half2 h[4];
            #pragma unroll
            for (int j = 0; j < 4; j++)
                h[j] = __floats2half2_rn(acc[i][2 * j] * di, acc[i][2 * j + 1] * di);
            uint4 pack;
            pack.x = *(unsigned*)&h[0];
            pack.y = *(unsigned*)&h[1];
            pack.z = *(unsigned*)&h[2];
            pack.w = *(unsigned*)&h[3];
            *(uint4*)&M[(size_t)gr * 64 + txc * 8] = pack;
        }
    }
}

// ---------------- half-warp fp16 aggregate (R8 structure: 1 node per warp) ----
template <bool WEIGHTED, bool RELU, bool ADDRES>
__global__ void __launch_bounds__(512) k_agg(const __half* __restrict__ M,
                                             const float* __restrict__ bias,
                                             const float* __restrict__ res,
                                             float* __restrict__ outp) {
    int lane = threadIdx.x & 31;
    int hid  = lane >> 4;
    int hl4  = (lane & 15) * 4;
    int row  = (blockIdx.x * 512 + threadIdx.x) >> 5;
    if (row >= N_NODES) return;

    int s  = g_rowptr[row];
    int en = g_rowptr[row + 1];
    float a0 = 0.f, a1 = 0.f, a2 = 0.f, a3 = 0.f;
    int e = s;
    #pragma unroll 1
    for (; e + 8 <= en; e += 8) {
        #pragma unroll
        for (int j = 0; j < 4; j++) {
            int2 cw = g_cw[e + 2 * j + hid];
            uint2 hv = *(const uint2*)&M[cw.x + hl4];
            float2 lo = __half22float2(*(__half2*)&hv.x);
            float2 hi = __half22float2(*(__half2*)&hv.y);
            if (WEIGHTED) {
                float w = __int_as_float(cw.y);
                a0 = fmaf(lo.x, w, a0); a1 = fmaf(lo.y, w, a1);
                a2 = fmaf(hi.x, w, a2); a3 = fmaf(hi.y, w, a3);
            } else {
                a0 += lo.x; a1 += lo.y; a2 += hi.x; a3 += hi.y;
            }
        }
    }
    for (; e + 2 <= en; e += 2) {
        int2 cw = g_cw[e + hid];
        uint2 hv = *(const uint2*)&M[cw.x + hl4];
        float2 lo = __half22float2(*(__half2*)&hv.x);
        float2 hi = __half22float2(*(__half2*)&hv.y);
        float w = WEIGHTED ? __int_as_float(cw.y) : 1.f;
        a0 = fmaf(lo.x, w, a0); a1 = fmaf(lo.y, w, a1);
        a2 = fmaf(hi.x, w, a2); a3 = fmaf(hi.y, w, a3);
    }
    if (e < en && hid == 0) {
        int2 cw = g_cw[e];
        uint2 hv = *(const uint2*)&M[cw.x + hl4];
        float2 lo = __half22float2(*(__half2*)&hv.x);
        float2 hi = __half22float2(*(__half2*)&hv.y);
        float w = WEIGHTED ? __int_as_float(cw.y) : 1.f;
        a0 = fmaf(lo.x, w, a0); a1 = fmaf(lo.y, w, a1);
        a2 = fmaf(hi.x, w, a2); a3 = fmaf(hi.y, w, a3);
    }
    a0 += __shfl_xor_sync(0xffffffffu, a0, 16);
    a1 += __shfl_xor_sync(0xffffffffu, a1, 16);
    a2 += __shfl_xor_sync(0xffffffffu, a2, 16);
    a3 += __shfl_xor_sync(0xffffffffu, a3, 16);

    if (hid == 0) {
        float di = g_dinv[row];
        float4 b = *(const float4*)&bias[hl4];
        float o0 = fmaf(a0, di, b.x);
        float o1 = fmaf(a1, di, b.y);
        float o2 = fmaf(a2, di, b.z);
        float o3 = fmaf(a3, di, b.w);
        if (RELU) {
            o0 = fmaxf(o0, 0.f); o1 = fmaxf(o1, 0.f);
            o2 = fmaxf(o2, 0.f); o3 = fmaxf(o3, 0.f);
        }
        if (ADDRES) {
            float4 r = *(const float4*)&res[(size_t)row * 64 + hl4];
            o0 += r.x; o1 += r.y; o2 += r.z; o3 += r.w;
        }
        *(float4*)&outp[(size_t)row * 64 + hl4] = make_float4(o0, o1, o2, o3);
    }
}

// ---------------- launch --------------------------------------------------------
extern "C" void kernel_launch(void* const* d_in, const int* in_sizes, int n_in,
                              void* d_out, int out_size) {
    const float* x  = (const float*)d_in[0];
    const void*  ei = d_in[1];
    const float* W0 = (const float*)d_in[2];
    const float* b0 = (const float*)d_in[3];
    const float* Ws = (const float*)d_in[4];
    const float* bs = (const float*)d_in[5];
    float* out = (float*)d_out;

    const float* Ws0 = Ws;
    const float* Ws1 = Ws + 64 * 64;
    const float* bs0 = bs;
    const float* bs1 = bs + 64;

    __half* M = nullptr;
    float *XT = nullptr, *H1 = nullptr;
    cudaGetSymbolAddress((void**)&M,  g_M);
    cudaGetSymbolAddress((void**)&XT, g_XT);
    cudaGetSymbolAddress((void**)&H1, g_h1);

    static cudaStream_t s2 = nullptr;
    static cudaEvent_t evF = nullptr, evG = nullptr;
    if (s2 == nullptr) {
        cudaStreamCreateWithFlags(&s2, cudaStreamNonBlocking);
        cudaEventCreateWithFlags(&evF, cudaEventDisableTiming);
        cudaEventCreateWithFlags(&evG, cudaEventDisableTiming);
    }

    const int GEMM_BLOCKS = (N_NODES + 127) / 128;           // 782
    const int AGG_BLOCKS  = (N_NODES * 32 + 511) / 512;      // 6250

    // ---- fork: gemm0 (independent of graph build) on side stream ----
    cudaEventRecord(evF, 0);
    cudaStreamWaitEvent(s2, evF, 0);
    k_gemm<128, false><<<GEMM_BLOCKS, 256, 0, s2>>>(x, W0, M);  // M = fp16(x@W0)
    cudaEventRecord(evG, s2);

    // ---- CSR build on default stream (concurrent with gemm0) ----
    k_count<<<(N_EDGES + 511) / 512, 512>>>(ei);
    k_scan1<<<NB_SCAN, 1024>>>();
    k_scan2f<<<NB_SCAN, 1024>>>();
    k_fill<<<(TOT + 511) / 512, 512>>>(ei);

    // ---- join, then the serial conv chain ----
    cudaStreamWaitEvent(0, evG, 0);
    // layer 0: XT = agg_w(M) + b0   (per-edge dinv[src] weights)
    k_agg<true, false, false><<<AGG_BLOCKS, 512>>>(M, b0, nullptr, XT);
    // layer 1: M = fp16(dinv*(XT@Ws0)); h1 = relu(agg(M)+bs0)
    k_gemm<64, true><<<GEMM_BLOCKS, 256>>>(XT, Ws0, M);
    k_agg<false, true, false><<<AGG_BLOCKS, 512>>>(M, bs0, nullptr, H1);
    // layer 2: M = fp16(dinv*(h1@Ws1)); out = relu(agg(M)+bs1) + XT
    k_gemm<64, true><<<GEMM_BLOCKS, 256>>>(H1, Ws1, M);
    k_agg<false, true, true><<<AGG_BLOCKS, 512>>>(M, bs1, XT, out);
}

// round 14
// speedup vs baseline: 1.5082x; 1.4585x over previous
#include <cuda_runtime.h>
#include <cuda_fp16.h>
#include <cuda_bf16.h>
#include <mma.h>

using namespace nvcuda::wmma;

#define N_NODES 100000
#define N_EDGES 1600000
#define TOT (N_EDGES + N_NODES)
#define NB_SCAN ((N_NODES + 1023) / 1024)   // 98

// ---------------- scratch -----------------------------------------------------
__device__ int    g_deg[N_NODES];
__device__ int    g_incl[N_NODES];
__device__ int    g_bsum[128];
__device__ int    g_rowptr[N_NODES + 1];
__device__ int    g_cursor[N_NODES];
__device__ int2   g_cw[TOT];             // {src*64, __float_as_int(dinv[src])}
__device__ float  g_dinv[N_NODES];
__device__ int    g_is64;

__device__ __align__(256) __half g_M[N_NODES * 64];   // fp16 message buffer
__device__ float g_XT[N_NODES * 64];                  // x_temp residual (fp32)
__device__ float g_h1[N_NODES * 64];                  // hidden (fp32)

// ---------------- helpers ------------------------------------------------------
__device__ __forceinline__ int load_idx(const void* ei, int pos) {
    if (g_is64) return (int)((const long long*)ei)[pos];
    return ((const int*)ei)[pos];
}

__global__ void k_init(const void* ei) {
    int i = blockIdx.x * blockDim.x + threadIdx.x;
    if (i < N_NODES) g_deg[i] = 1;   // self loop
    if (i == 0) {
        const long long* p = (const long long*)ei;
        int ok64 = 1;
        #pragma unroll
        for (int j = 0; j < 16; j++) {
            long long v = p[j];
            if (v < 0 || v >= N_NODES) ok64 = 0;
        }
        g_is64 = ok64;
    }
}

__global__ void k_count(const void* ei) {
    int t = blockIdx.x * blockDim.x + threadIdx.x;
    if (t < N_EDGES) atomicAdd(&g_deg[load_idx(ei, N_EDGES + t)], 1);
}

__global__ void k_scan1() {
    __shared__ int s[1024];
    int tid = threadIdx.x;
    int i = blockIdx.x * 1024 + tid;
    int v = (i < N_NODES) ? g_deg[i] : 0;
    s[tid] = v;
    __syncthreads();
    #pragma unroll
    for (int off = 1; off < 1024; off <<= 1) {
        int t = (tid >= off) ? s[tid - off] : 0;
        __syncthreads();
        s[tid] += t;
        __syncthreads();
    }
    if (i < N_NODES) g_incl[i] = s[tid];
    if (tid == 1023) g_bsum[blockIdx.x] = s[1023];
}

__global__ void k_scan2f() {
    __shared__ int sb[128];
    int tid = threadIdx.x;
    if (tid < 128) sb[tid] = (tid < NB_SCAN) ? g_bsum[tid] : 0;
    __syncthreads();
    int boff = 0;
    for (int j = 0; j < (int)blockIdx.x; j++) boff += sb[j];
    int i = blockIdx.x * 1024 + tid;
    if (i < N_NODES) {
        int rp = g_incl[i] - g_deg[i] + boff;
        g_rowptr[i] = rp;
        g_cursor[i] = rp;
        g_dinv[i]   = rsqrtf((float)g_deg[i]);
    }
    if (i == 0) g_rowptr[N_NODES] = TOT;
}

__global__ void k_fill(const void* ei) {
    int t = blockIdx.x * blockDim.x + threadIdx.x;
    if (t < N_EDGES) {
        int s = load_idx(ei, t);
        int d = load_idx(ei, N_EDGES + t);
        int pos = atomicAdd(&g_cursor[d], 1);
        g_cw[pos] = make_int2(s * 64, __float_as_int(g_dinv[s]));
    } else if (t < TOT) {
        int i = t - N_EDGES;
        int pos = atomicAdd(&g_cursor[i], 1);
        g_cw[pos] = make_int2(i * 64, __float_as_int(g_dinv[i]));
    }
}

// ---------------- tensor-core GEMM: M16 = [dinv *] fp16(X @ W) ----------------
// block = 64 rows x 64 cols, 8 warps, wmma m16n16k16 fp16 -> fp32 acc.
// Cs (fp32 epilogue buffer) aliases As/Bs after the mma loop.
template <int K, bool SCALE>
__global__ void __launch_bounds__(256) k_gemm(const float* __restrict__ X,
                                              const float* __restrict__ W,
                                              __half* __restrict__ M) {
    constexpr int LDA = K + 8;        // halves; mult of 8
    constexpr int LDB = 72;
    constexpr int LDC = 72;
    constexpr int AS_BYTES = 64 * LDA * 2;
    constexpr int BS_BYTES = K * LDB * 2;
    constexpr int CS_BYTES = 64 * LDC * 4;
    constexpr int BUF = (AS_BYTES + BS_BYTES) > CS_BYTES ? (AS_BYTES + BS_BYTES) : CS_BYTES;
    __shared__ __align__(16) char buf[BUF];
    __half* As = (__half*)buf;
    __half* Bs = (__half*)(buf + AS_BYTES);
    float*  Cs = (float*)buf;        // alias (valid after post-mma syncthreads)

    int tid = threadIdx.x;
    int block_row = blockIdx.x * 64;

    // stage A: 64 x K fp32 -> fp16
    for (int idx = tid; idx < 64 * K / 4; idx += 256) {
        int r  = idx / (K / 4);
        int c4 = (idx % (K / 4)) * 4;
        int gr = block_row + r;
        float4 v = (gr < N_NODES) ? *(const float4*)&X[(size_t)gr * K + c4]
                                  : make_float4(0.f, 0.f, 0.f, 0.f);
        *(__half2*)&As[r * LDA + c4]     = __floats2half2_rn(v.x, v.y);
        *(__half2*)&As[r * LDA + c4 + 2] = __floats2half2_rn(v.z, v.w);
    }
    // stage B: K x 64 fp32 -> fp16
    for (int idx = tid; idx < K * 16; idx += 256) {
        int r  = idx / 16;
        int c4 = (idx % 16) * 4;
        float4 v = *(const float4*)&W[r * 64 + c4];
        *(__half2*)&Bs[r * LDB + c4]     = __floats2half2_rn(v.x, v.y);
        *(__half2*)&Bs[r * LDB + c4 + 2] = __floats2half2_rn(v.z, v.w);
    }
    __syncthreads();

    int warp = tid >> 5;
    int wc = warp & 3;    // col tile
    int wr = warp >> 2;   // row half (32 rows each)

    fragment<accumulator, 16, 16, 16, float> acc0, acc1;
    fill_fragment(acc0, 0.f);
    fill_fragment(acc1, 0.f);
    fragment<matrix_a, 16, 16, 16, __half, row_major> fa;
    fragment<matrix_b, 16, 16, 16, __half, row_major> fb;

    #pragma unroll
    for (int k0 = 0; k0 < K; k0 += 16) {
        load_matrix_sync(fb, &Bs[k0 * LDB + wc * 16], LDB);
        load_matrix_sync(fa, &As[(wr * 32) * LDA + k0], LDA);
        mma_sync(acc0, fa, fb, acc0);
        load_matrix_sync(fa, &As[(wr * 32 + 16) * LDA + k0], LDA);
        mma_sync(acc1, fa, fb, acc1);
    }
    __syncthreads();   // all warps done reading As/Bs before Cs overwrites

    store_matrix_sync(&Cs[(wr * 32) * LDC + wc * 16],      acc0, LDC, mem_row_major);
    store_matrix_sync(&Cs[(wr * 32 + 16) * LDC + wc * 16], acc1, LDC, mem_row_major);
    __syncthreads();

    // epilogue: scale by dinv, pack fp16, vector store
    for (int idx = tid; idx < 64 * 8; idx += 256) {
        int r  = idx >> 3;
        int c8 = (idx & 7) * 8;
        int gr = block_row + r;
        if (gr < N_NODES) {
            float di = SCALE ? g_dinv[gr] : 1.f;
            const float* cp = &Cs[r * LDC + c8];
            __half2 h[4];
            #pragma unroll
            for (int j = 0; j < 4; j++)
                h[j] = __floats2half2_rn(cp[2 * j] * di, cp[2 * j + 1] * di);
            uint4 pack;
            pack.x = *(unsigned*)&h[0];
            pack.y = *(unsigned*)&h[1];
            pack.z = *(unsigned*)&h[2];
            pack.w = *(unsigned*)&h[3];
            *(uint4*)&M[(size_t)gr * 64 + c8] = pack;
        }
    }
}

// ---------------- half-warp fp16 aggregate (R8 structure) ---------------------
template <bool WEIGHTED, bool RELU, bool ADDRES>
__global__ void __launch_bounds__(512) k_agg(const __half* __restrict__ M,
                                             const float* __restrict__ bias,
                                             const float* __restrict__ res,
                                             float* __restrict__ outp) {
    int lane = threadIdx.x & 31;
    int hid  = lane >> 4;
    int hl4  = (lane & 15) * 4;
    int row  = (blockIdx.x * 512 + threadIdx.x) >> 5;
    if (row >= N_NODES) return;

    int s  = g_rowptr[row];
    int en = g_rowptr[row + 1];
    float a0 = 0.f, a1 = 0.f, a2 = 0.f, a3 = 0.f;
    int e = s;
    #pragma unroll 1
    for (; e + 8 <= en; e += 8) {
        #pragma unroll
        for (int j = 0; j < 4; j++) {
            int2 cw = g_cw[e + 2 * j + hid];
            uint2 hv = *(const uint2*)&M[cw.x + hl4];
            float2 lo = __half22float2(*(__half2*)&hv.x);
            float2 hi = __half22float2(*(__half2*)&hv.y);
            if (WEIGHTED) {
                float w = __int_as_float(cw.y);
                a0 = fmaf(lo.x, w, a0); a1 = fmaf(lo.y, w, a1);
                a2 = fmaf(hi.x, w, a2); a3 = fmaf(hi.y, w, a3);
            } else {
                a0 += lo.x; a1 += lo.y; a2 += hi.x; a3 += hi.y;
            }
        }
    }
    for (; e + 2 <= en; e += 2) {
        int2 cw = g_cw[e + hid];
        uint2 hv = *(const uint2*)&M[cw.x + hl4];
        float2 lo = __half22float2(*(__half2*)&hv.x);
        float2 hi = __half22float2(*(__half2*)&hv.y);
        float w = WEIGHTED ? __int_as_float(cw.y) : 1.f;
        a0 = fmaf(lo.x, w, a0); a1 = fmaf(lo.y, w, a1);
        a2 = fmaf(hi.x, w, a2); a3 = fmaf(hi.y, w, a3);
    }
    if (e < en && hid == 0) {
        int2 cw = g_cw[e];
        uint2 hv = *(const uint2*)&M[cw.x + hl4];
        float2 lo = __half22float2(*(__half2*)&hv.x);
        float2 hi = __half22float2(*(__half2*)&hv.y);
        float w = WEIGHTED ? __int_as_float(cw.y) : 1.f;
        a0 = fmaf(lo.x, w, a0); a1 = fmaf(lo.y, w, a1);
        a2 = fmaf(hi.x, w, a2); a3 = fmaf(hi.y, w, a3);
    }
    a0 += __shfl_xor_sync(0xffffffffu, a0, 16);
    a1 += __shfl_xor_sync(0xffffffffu, a1, 16);
    a2 += __shfl_xor_sync(0xffffffffu, a2, 16);
    a3 += __shfl_xor_sync(0xffffffffu, a3, 16);

    if (hid == 0) {
        float di = g_dinv[row];
        float4 b = *(const float4*)&bias[hl4];
        float o0 = fmaf(a0, di, b.x);
        float o1 = fmaf(a1, di, b.y);
        float o2 = fmaf(a2, di, b.z);
        float o3 = fmaf(a3, di, b.w);
        if (RELU) {
            o0 = fmaxf(o0, 0.f); o1 = fmaxf(o1, 0.f);
            o2 = fmaxf(o2, 0.f); o3 = fmaxf(o3, 0.f);
        }
        if (ADDRES) {
            float4 r = *(const float4*)&res[(size_t)row * 64 + hl4];
            o0 += r.x; o1 += r.y; o2 += r.z; o3 += r.w;
        }
        *(float4*)&outp[(size_t)row * 64 + hl4] = make_float4(o0, o1, o2, o3);
    }
}

// ---------------- launch --------------------------------------------------------
extern "C" void kernel_launch(void* const* d_in, const int* in_sizes, int n_in,
                              void* d_out, int out_size) {
    const float* x  = (const float*)d_in[0];
    const void*  ei = d_in[1];
    const float* W0 = (const float*)d_in[2];
    const float* b0 = (const float*)d_in[3];
    const float* Ws = (const float*)d_in[4];
    const float* bs = (const float*)d_in[5];
    float* out = (float*)d_out;

    const float* Ws0 = Ws;
    const float* Ws1 = Ws + 64 * 64;
    const float* bs0 = bs;
    const float* bs1 = bs + 64;

    __half* M = nullptr;
    float *XT = nullptr, *H1 = nullptr;
    cudaGetSymbolAddress((void**)&M,  g_M);
    cudaGetSymbolAddress((void**)&XT, g_XT);
    cudaGetSymbolAddress((void**)&H1, g_h1);

    static cudaStream_t s2 = nullptr;
    static cudaEvent_t evF = nullptr, evG = nullptr;
    if (s2 == nullptr) {
        cudaStreamCreateWithFlags(&s2, cudaStreamNonBlocking);
        cudaEventCreateWithFlags(&evF, cudaEventDisableTiming);
        cudaEventCreateWithFlags(&evG, cudaEventDisableTiming);
    }

    const int GEMM_BLOCKS = (N_NODES + 63) / 64;             // 1563
    const int AGG_BLOCKS  = (N_NODES * 32 + 511) / 512;      // 6250

    // ---- fork: gemm0 (independent of graph build) on side stream ----
    cudaEventRecord(evF, 0);
    cudaStreamWaitEvent(s2, evF, 0);
    k_gemm<128, false><<<GEMM_BLOCKS, 256, 0, s2>>>(x, W0, M);  // M = fp16(x@W0)
    cudaEventRecord(evG, s2);

    // ---- CSR build on default stream (concurrent with gemm0) ----
    k_init<<<(N_NODES + 255) / 256, 256>>>(ei);
    k_count<<<(N_EDGES + 511) / 512, 512>>>(ei);
    k_scan1<<<NB_SCAN, 1024>>>();
    k_scan2f<<<NB_SCAN, 1024>>>();
    k_fill<<<(TOT + 511) / 512, 512>>>(ei);

    // ---- join, then the serial conv chain ----
    cudaStreamWaitEvent(0, evG, 0);
    // layer 0: XT = agg_w(M) + b0   (per-edge dinv[src] weights)
    k_agg<true, false, false><<<AGG_BLOCKS, 512>>>(M, b0, nullptr, XT);
    // layer 1: M = fp16(dinv*(XT@Ws0)); h1 = relu(agg(M)+bs0)
    k_gemm<64, true><<<GEMM_BLOCKS, 256>>>(XT, Ws0, M);
    k_agg<false, true, false><<<AGG_BLOCKS, 512>>>(M, bs0, nullptr, H1);
    // layer 2: M = fp16(dinv*(h1@Ws1)); out = relu(agg(M)+bs1) + XT
    k_gemm<64, true><<<GEMM_BLOCKS, 256>>>(H1, Ws1, M);
    k_agg<false, true, true><<<AGG_BLOCKS, 512>>>(M, bs1, XT, out);
}

// round 15
// speedup vs baseline: 1.5429x; 1.0230x over previous
#include <cuda_runtime.h>
#include <cuda_fp16.h>
#include <cuda_bf16.h>
#include <mma.h>

using namespace nvcuda::wmma;

#define N_NODES 100000
#define N_EDGES 1600000
#define TOT (N_EDGES + N_NODES)
#define NB_SCAN ((N_NODES + 1023) / 1024)   // 98
#define NHALF 49984                          // 64-aligned split for pipelining
#define NREST (N_NODES - NHALF)              // 50016

// ---------------- scratch -----------------------------------------------------
__device__ int    g_deg[N_NODES];
__device__ int    g_incl[N_NODES];
__device__ int    g_bsum[128];
__device__ int    g_rowptr[N_NODES + 1];
__device__ int    g_cursor[N_NODES];
__device__ int2   g_cw[TOT];             // {src*64, __float_as_int(dinv[src])}
__device__ float  g_dinv[N_NODES];
__device__ int    g_is64;

__device__ __align__(256) __half g_MA[N_NODES * 64];   // message ping
__device__ __align__(256) __half g_MB[N_NODES * 64];   // message pong
__device__ __align__(256) __half g_XT16[N_NODES * 64]; // x_temp residual (fp16)
__device__ __align__(256) __half g_H116[N_NODES * 64]; // hidden (fp16)

// ---------------- helpers ------------------------------------------------------
__device__ __forceinline__ int load_idx(const void* ei, int pos) {
    if (g_is64) return (int)((const long long*)ei)[pos];
    return ((const int*)ei)[pos];
}

__global__ void k_init(const void* ei) {
    int i = blockIdx.x * blockDim.x + threadIdx.x;
    if (i < N_NODES) g_deg[i] = 1;   // self loop
    if (i == 0) {
        const long long* p = (const long long*)ei;
        int ok64 = 1;
        #pragma unroll
        for (int j = 0; j < 16; j++) {
            long long v = p[j];
            if (v < 0 || v >= N_NODES) ok64 = 0;
        }
        g_is64 = ok64;
    }
}

__global__ void k_count(const void* ei) {
    int t = blockIdx.x * blockDim.x + threadIdx.x;
    if (t < N_EDGES) atomicAdd(&g_deg[load_idx(ei, N_EDGES + t)], 1);
}

// warp-shuffle block scan (inclusive)
__global__ void k_scan1() {
    __shared__ int wsum[32];
    int tid = threadIdx.x;
    int i = blockIdx.x * 1024 + tid;
    int v = (i < N_NODES) ? g_deg[i] : 0;
    int lane = tid & 31, w = tid >> 5;
    int sv = v;
    #pragma unroll
    for (int off = 1; off < 32; off <<= 1) {
        int t = __shfl_up_sync(0xffffffffu, sv, off);
        if (lane >= off) sv += t;
    }
    if (lane == 31) wsum[w] = sv;
    __syncthreads();
    if (w == 0) {
        int s = wsum[lane];
        #pragma unroll
        for (int off = 1; off < 32; off <<= 1) {
            int t = __shfl_up_sync(0xffffffffu, s, off);
            if (lane >= off) s += t;
        }
        wsum[lane] = s;
    }
    __syncthreads();
    int add = (w > 0) ? wsum[w - 1] : 0;
    if (i < N_NODES) g_incl[i] = sv + add;
    if (tid == 1023) g_bsum[blockIdx.x] = sv + add;
}

__global__ void k_scan2f() {
    __shared__ int sb[128];
    __shared__ int sboff;
    int tid = threadIdx.x;
    if (tid < 128) sb[tid] = (tid < NB_SCAN) ? g_bsum[tid] : 0;
    __syncthreads();
    if (tid == 0) {
        int b = 0;
        for (int j = 0; j < (int)blockIdx.x; j++) b += sb[j];
        sboff = b;
    }
    __syncthreads();
    int boff = sboff;
    int i = blockIdx.x * 1024 + tid;
    if (i < N_NODES) {
        int rp = g_incl[i] - g_deg[i] + boff;
        g_rowptr[i] = rp;
        g_cursor[i] = rp;
        g_dinv[i]   = rsqrtf((float)g_deg[i]);
    }
    if (i == 0) g_rowptr[N_NODES] = TOT;
}

__global__ void k_fill(const void* ei) {
    int t = blockIdx.x * blockDim.x + threadIdx.x;
    if (t < N_EDGES) {
        int s = load_idx(ei, t);
        int d = load_idx(ei, N_EDGES + t);
        int pos = atomicAdd(&g_cursor[d], 1);
        g_cw[pos] = make_int2(s * 64, __float_as_int(g_dinv[s]));
    } else if (t < TOT) {
        int i = t - N_EDGES;
        int pos = atomicAdd(&g_cursor[i], 1);
        g_cw[pos] = make_int2(i * 64, __float_as_int(g_dinv[i]));
    }
}

// ---------------- tensor-core GEMM: M16 = [dinv *] fp16(X @ W) ----------------
// block = 64 rows x 64 cols, 8 warps, wmma m16n16k16 fp16 -> fp32 acc.
// IN16: input already fp16 (no convert in stage). Row window [row_base, +nrows).
template <int K, bool IN16, bool SCALE>
__global__ void __launch_bounds__(256) k_gemm(const void* __restrict__ Xv,
                                              const float* __restrict__ W,
                                              __half* __restrict__ M,
                                              int row_base) {
    constexpr int LDA = K + 8;
    constexpr int LDB = 72;
    constexpr int LDC = 72;
    constexpr int AS_BYTES = 64 * LDA * 2;
    constexpr int BS_BYTES = K * LDB * 2;
    constexpr int CS_BYTES = 64 * LDC * 4;
    constexpr int BUF = (AS_BYTES + BS_BYTES) > CS_BYTES ? (AS_BYTES + BS_BYTES) : CS_BYTES;
    __shared__ __align__(16) char buf[BUF];
    __half* As = (__half*)buf;
    __half* Bs = (__half*)(buf + AS_BYTES);
    float*  Cs = (float*)buf;

    int tid = threadIdx.x;
    int block_row = row_base + blockIdx.x * 64;

    if (IN16) {
        const __half* X16 = (const __half*)Xv;
        for (int idx = tid; idx < 64 * K / 8; idx += 256) {
            int r  = idx / (K / 8);
            int c8 = (idx % (K / 8)) * 8;
            int gr = block_row + r;
            uint4 v = (gr < N_NODES) ? *(const uint4*)&X16[(size_t)gr * K + c8]
                                     : make_uint4(0u, 0u, 0u, 0u);
            *(uint4*)&As[r * LDA + c8] = v;
        }
    } else {
        const float* X = (const float*)Xv;
        for (int idx = tid; idx < 64 * K / 4; idx += 256) {
            int r  = idx / (K / 4);
            int c4 = (idx % (K / 4)) * 4;
            int gr = block_row + r;
            float4 v = (gr < N_NODES) ? *(const float4*)&X[(size_t)gr * K + c4]
                                      : make_float4(0.f, 0.f, 0.f, 0.f);
            *(__half2*)&As[r * LDA + c4]     = __floats2half2_rn(v.x, v.y);
            *(__half2*)&As[r * LDA + c4 + 2] = __floats2half2_rn(v.z, v.w);
        }
    }
    for (int idx = tid; idx < K * 16; idx += 256) {
        int r  = idx / 16;
        int c4 = (idx % 16) * 4;
        float4 v = *(const float4*)&W[r * 64 + c4];
        *(__half2*)&Bs[r * LDB + c4]     = __floats2half2_rn(v.x, v.y);
        *(__half2*)&Bs[r * LDB + c4 + 2] = __floats2half2_rn(v.z, v.w);
    }
    __syncthreads();

    int warp = tid >> 5;
    int wc = warp & 3;
    int wr = warp >> 2;

    fragment<accumulator, 16, 16, 16, float> acc0, acc1;
    fill_fragment(acc0, 0.f);
    fill_fragment(acc1, 0.f);
    fragment<matrix_a, 16, 16, 16, __half, row_major> fa;
    fragment<matrix_b, 16, 16, 16, __half, row_major> fb;

    #pragma unroll
    for (int k0 = 0; k0 < K; k0 += 16) {
        load_matrix_sync(fb, &Bs[k0 * LDB + wc * 16], LDB);
        load_matrix_sync(fa, &As[(wr * 32) * LDA + k0], LDA);
        mma_sync(acc0, fa, fb, acc0);
        load_matrix_sync(fa, &As[(wr * 32 + 16) * LDA + k0], LDA);
        mma_sync(acc1, fa, fb, acc1);
    }
    __syncthreads();

    store_matrix_sync(&Cs[(wr * 32) * LDC + wc * 16],      acc0, LDC, mem_row_major);
    store_matrix_sync(&Cs[(wr * 32 + 16) * LDC + wc * 16], acc1, LDC, mem_row_major);
    __syncthreads();

    for (int idx = tid; idx < 64 * 8; idx += 256) {
        int r  = idx >> 3;
        int c8 = (idx & 7) * 8;
        int gr = block_row + r;
        if (gr < N_NODES) {
            float di = SCALE ? g_dinv[gr] : 1.f;
            const float* cp = &Cs[r * LDC + c8];
            __half2 h[4];
            #pragma unroll
            for (int j = 0; j < 4; j++)
                h[j] = __floats2half2_rn(cp[2 * j] * di, cp[2 * j + 1] * di);
            uint4 pack;
            pack.x = *(unsigned*)&h[0];
            pack.y = *(unsigned*)&h[1];
            pack.z = *(unsigned*)&h[2];
            pack.w = *(unsigned*)&h[3];
            *(uint4*)&M[(size_t)gr * 64 + c8] = pack;
        }
    }
}

// ---------------- half-warp fp16 aggregate (row window) -----------------------
template <bool WEIGHTED, bool RELU, bool OUT16, bool ADDRES>
__global__ void __launch_bounds__(512) k_agg(const __half* __restrict__ M,
                                             const float* __restrict__ bias,
                                             const __half* __restrict__ res16,
                                             void* __restrict__ outp,
                                             int row_base, int row_count) {
    int lane = threadIdx.x & 31;
    int hid  = lane >> 4;
    int hl4  = (lane & 15) * 4;
    int r    = (blockIdx.x * 512 + threadIdx.x) >> 5;
    if (r >= row_count) return;
    int row = row_base + r;

    int s  = g_rowptr[row];
    int en = g_rowptr[row + 1];
    float a0 = 0.f, a1 = 0.f, a2 = 0.f, a3 = 0.f;
    int e = s;
    #pragma unroll 1
    for (; e + 8 <= en; e += 8) {
        #pragma unroll
        for (int j = 0; j < 4; j++) {
            int2 cw = g_cw[e + 2 * j + hid];
            uint2 hv = *(const uint2*)&M[cw.x + hl4];
            float2 lo = __half22float2(*(__half2*)&hv.x);
            float2 hi = __half22float2(*(__half2*)&hv.y);
            if (WEIGHTED) {
                float w = __int_as_float(cw.y);
                a0 = fmaf(lo.x, w, a0); a1 = fmaf(lo.y, w, a1);
                a2 = fmaf(hi.x, w, a2); a3 = fmaf(hi.y, w, a3);
            } else {
                a0 += lo.x; a1 += lo.y; a2 += hi.x; a3 += hi.y;
            }
        }
    }
    for (; e + 2 <= en; e += 2) {
        int2 cw = g_cw[e + hid];
        uint2 hv = *(const uint2*)&M[cw.x + hl4];
        float2 lo = __half22float2(*(__half2*)&hv.x);
        float2 hi = __half22float2(*(__half2*)&hv.y);
        float w = WEIGHTED ? __int_as_float(cw.y) : 1.f;
        a0 = fmaf(lo.x, w, a0); a1 = fmaf(lo.y, w, a1);
        a2 = fmaf(hi.x, w, a2); a3 = fmaf(hi.y, w, a3);
    }
    if (e < en && hid == 0) {
        int2 cw = g_cw[e];
        uint2 hv = *(const uint2*)&M[cw.x + hl4];
        float2 lo = __half22float2(*(__half2*)&hv.x);
        float2 hi = __half22float2(*(__half2*)&hv.y);
        float w = WEIGHTED ? __int_as_float(cw.y) : 1.f;
        a0 = fmaf(lo.x, w, a0); a1 = fmaf(lo.y, w, a1);
        a2 = fmaf(hi.x, w, a2); a3 = fmaf(hi.y, w, a3);
    }
    a0 += __shfl_xor_sync(0xffffffffu, a0, 16);
    a1 += __shfl_xor_sync(0xffffffffu, a1, 16);
    a2 += __shfl_xor_sync(0xffffffffu, a2, 16);
    a3 += __shfl_xor_sync(0xffffffffu, a3, 16);

    if (hid == 0) {
        float di = g_dinv[row];
        float4 b = *(const float4*)&bias[hl4];
        float o0 = fmaf(a0, di, b.x);
        float o1 = fmaf(a1, di, b.y);
        float o2 = fmaf(a2, di, b.z);
        float o3 = fmaf(a3, di, b.w);
        if (RELU) {
            o0 = fmaxf(o0, 0.f); o1 = fmaxf(o1, 0.f);
            o2 = fmaxf(o2, 0.f); o3 = fmaxf(o3, 0.f);
        }
        if (ADDRES) {
            uint2 rv = *(const uint2*)&res16[(size_t)row * 64 + hl4];
            float2 rlo = __half22float2(*(__half2*)&rv.x);
            float2 rhi = __half22float2(*(__half2*)&rv.y);
            o0 += rlo.x; o1 += rlo.y; o2 += rhi.x; o3 += rhi.y;
        }
        if (OUT16) {
            __half2 p0 = __floats2half2_rn(o0, o1);
            __half2 p1 = __floats2half2_rn(o2, o3);
            *(uint2*)&((__half*)outp)[(size_t)row * 64 + hl4] =
                make_uint2(*(unsigned*)&p0, *(unsigned*)&p1);
        } else {
            *(float4*)&((float*)outp)[(size_t)row * 64 + hl4] =
                make_float4(o0, o1, o2, o3);
        }
    }
}

// ---------------- launch --------------------------------------------------------
extern "C" void kernel_launch(void* const* d_in, const int* in_sizes, int n_in,
                              void* d_out, int out_size) {
    const float* x  = (const float*)d_in[0];
    const void*  ei = d_in[1];
    const float* W0 = (const float*)d_in[2];
    const float* b0 = (const float*)d_in[3];
    const float* Ws = (const float*)d_in[4];
    const float* bs = (const float*)d_in[5];
    float* out = (float*)d_out;

    const float* Ws0 = Ws;
    const float* Ws1 = Ws + 64 * 64;
    const float* bs0 = bs;
    const float* bs1 = bs + 64;

    __half *MA = nullptr, *MB = nullptr, *XT16 = nullptr, *H116 = nullptr;
    cudaGetSymbolAddress((void**)&MA,   g_MA);
    cudaGetSymbolAddress((void**)&MB,   g_MB);
    cudaGetSymbolAddress((void**)&XT16, g_XT16);
    cudaGetSymbolAddress((void**)&H116, g_H116);

    static cudaStream_t s2 = nullptr;
    static cudaEvent_t evF, evG0, evA0, evA1, evG1, evB0, evB1, evG2;
    if (s2 == nullptr) {
        cudaStreamCreateWithFlags(&s2, cudaStreamNonBlocking);
        cudaEventCreateWithFlags(&evF,  cudaEventDisableTiming);
        cudaEventCreateWithFlags(&evG0, cudaEventDisableTiming);
        cudaEventCreateWithFlags(&evA0, cudaEventDisableTiming);
        cudaEventCreateWithFlags(&evA1, cudaEventDisableTiming);
        cudaEventCreateWithFlags(&evG1, cudaEventDisableTiming);
        cudaEventCreateWithFlags(&evB0, cudaEventDisableTiming);
        cudaEventCreateWithFlags(&evB1, cudaEventDisableTiming);
        cudaEventCreateWithFlags(&evG2, cudaEventDisableTiming);
    }

    const int GB_ALL = (N_NODES + 63) / 64;   // 1563
    const int GB_H0  = NHALF / 64;            // 781
    const int GB_H1  = (NREST + 63) / 64;     // 782
    const int AB_H0  = (NHALF * 32) / 512;    // 3124
    const int AB_H1  = (NREST * 32) / 512;    // 3126
    const int AB_ALL = (N_NODES * 32 + 511) / 512;

    // ---- fork: gemm0 on side stream, CSR build on default ----
    cudaEventRecord(evF, 0);
    cudaStreamWaitEvent(s2, evF, 0);
    k_gemm<128, false, false><<<GB_ALL, 256, 0, s2>>>(x, W0, MA, 0);
    cudaEventRecord(evG0, s2);

    k_init<<<(N_NODES + 255) / 256, 256>>>(ei);
    k_count<<<(N_EDGES + 511) / 512, 512>>>(ei);
    k_scan1<<<NB_SCAN, 1024>>>();
    k_scan2f<<<NB_SCAN, 1024>>>();
    k_fill<<<(TOT + 511) / 512, 512>>>(ei);

    cudaStreamWaitEvent(0, evG0, 0);

    // ---- layer 0: agg (weighted) in halves -> XT16; gemm1 halves overlap on s2
    k_agg<true, false, true, false><<<AB_H0, 512>>>(MA, b0, nullptr, XT16, 0, NHALF);
    cudaEventRecord(evA0, 0);
    k_agg<true, false, true, false><<<AB_H1, 512>>>(MA, b0, nullptr, XT16, NHALF, NREST);
    cudaEventRecord(evA1, 0);

    cudaStreamWaitEvent(s2, evA0, 0);
    k_gemm<64, true, true><<<GB_H0, 256, 0, s2>>>(XT16, Ws0, MB, 0);
    cudaStreamWaitEvent(s2, evA1, 0);
    k_gemm<64, true, true><<<GB_H1, 256, 0, s2>>>(XT16, Ws0, MB, NHALF);
    cudaEventRecord(evG1, s2);

    // ---- layer 1: agg halves -> H116; gemm2 halves overlap on s2
    cudaStreamWaitEvent(0, evG1, 0);
    k_agg<false, true, true, false><<<AB_H0, 512>>>(MB, bs0, nullptr, H116, 0, NHALF);
    cudaEventRecord(evB0, 0);
    k_agg<false, true, true, false><<<AB_H1, 512>>>(MB, bs0, nullptr, H116, NHALF, NREST);
    cudaEventRecord(evB1, 0);

    cudaStreamWaitEvent(s2, evB0, 0);
    k_gemm<64, true, true><<<GB_H0, 256, 0, s2>>>(H116, Ws1, MA, 0);
    cudaStreamWaitEvent(s2, evB1, 0);
    k_gemm<64, true, true><<<GB_H1, 256, 0, s2>>>(H116, Ws1, MA, NHALF);
    cudaEventRecord(evG2, s2);

    // ---- layer 2: agg + residual -> out (fp32)
    cudaStreamWaitEvent(0, evG2, 0);
    k_agg<false, true, false, true><<<AB_ALL, 512>>>(MA, bs1, XT16, out, 0, N_NODES);
}

// round 16
// speedup vs baseline: 1.5657x; 1.0148x over previous
#include <cuda_runtime.h>
#include <cuda_fp16.h>
#include <cuda_bf16.h>
#include <mma.h>

using namespace nvcuda::wmma;

#define N_NODES 100000
#define N_EDGES 1600000
#define TOT (N_EDGES + N_NODES)
#define NB_SCAN ((N_NODES + 1023) / 1024)   // 98
#define NHALF 49984                          // 64-aligned split for pipelining
#define NREST (N_NODES - NHALF)              // 50016

// ---------------- scratch (g_deg zero at module load; reset each run) ---------
__device__ int    g_deg[N_NODES];
__device__ int    g_incl[N_NODES];
__device__ int    g_bsum[128];
__device__ int    g_rowptr[N_NODES + 1];
__device__ int    g_cursor[N_NODES];
__device__ int2   g_cw[TOT];             // {src*64, __float_as_int(dinv[src])}
__device__ float  g_dinv[N_NODES];

__device__ __align__(256) __half g_MA[N_NODES * 64];   // message ping
__device__ __align__(256) __half g_MB[N_NODES * 64];   // message pong
__device__ __align__(256) __half g_XT16[N_NODES * 64]; // x_temp residual (fp16)
__device__ __align__(256) __half g_H116[N_NODES * 64]; // hidden (fp16)

// ---------------- per-block edge dtype detect (thread 0 -> shared) ------------
__device__ __forceinline__ bool block_detect64(const void* ei, int* s_flag) {
    if (threadIdx.x == 0) {
        const long long* p = (const long long*)ei;
        int ok = 1;
        #pragma unroll
        for (int j = 0; j < 16; j++) {
            long long v = p[j];
            if (v < 0 || v >= N_NODES) ok = 0;
        }
        *s_flag = ok;
    }
    __syncthreads();
    return *s_flag != 0;
}

__global__ void k_count(const void* ei) {
    __shared__ int s_is64;
    bool is64 = block_detect64(ei, &s_is64);
    int t = blockIdx.x * blockDim.x + threadIdx.x;
    if (t < N_EDGES) {
        int d = is64 ? (int)((const long long*)ei)[N_EDGES + t]
                     : ((const int*)ei)[N_EDGES + t];
        atomicAdd(&g_deg[d], 1);
    }
}

// warp-shuffle block scan (inclusive) over deg+1 (self loop)
__global__ void k_scan1() {
    __shared__ int wsum[32];
    int tid = threadIdx.x;
    int i = blockIdx.x * 1024 + tid;
    int v = (i < N_NODES) ? (g_deg[i] + 1) : 0;
    int lane = tid & 31, w = tid >> 5;
    int sv = v;
    #pragma unroll
    for (int off = 1; off < 32; off <<= 1) {
        int t = __shfl_up_sync(0xffffffffu, sv, off);
        if (lane >= off) sv += t;
    }
    if (lane == 31) wsum[w] = sv;
    __syncthreads();
    if (w == 0) {
        int s = wsum[lane];
        #pragma unroll
        for (int off = 1; off < 32; off <<= 1) {
            int t = __shfl_up_sync(0xffffffffu, s, off);
            if (lane >= off) s += t;
        }
        wsum[lane] = s;
    }
    __syncthreads();
    int add = (w > 0) ? wsum[w - 1] : 0;
    if (i < N_NODES) g_incl[i] = sv + add;
    if (tid == 1023) g_bsum[blockIdx.x] = sv + add;
}

__global__ void k_scan2f() {
    __shared__ int sb[128];
    __shared__ int sboff;
    int tid = threadIdx.x;
    if (tid < 128) sb[tid] = (tid < NB_SCAN) ? g_bsum[tid] : 0;
    __syncthreads();
    if (tid == 0) {
        int b = 0;
        for (int j = 0; j < (int)blockIdx.x; j++) b += sb[j];
        sboff = b;
    }
    __syncthreads();
    int boff = sboff;
    int i = blockIdx.x * 1024 + tid;
    if (i < N_NODES) {
        int d  = g_deg[i] + 1;              // incl self loop
        g_deg[i] = 0;                       // restore zero-state for next replay
        int rp = g_incl[i] - d + boff;
        g_rowptr[i] = rp;
        g_cursor[i] = rp;
        g_dinv[i]   = rsqrtf((float)d);
    }
    if (i == 0) g_rowptr[N_NODES] = TOT;
}

__global__ void k_fill(const void* ei) {
    __shared__ int s_is64;
    bool is64 = block_detect64(ei, &s_is64);
    int t = blockIdx.x * blockDim.x + threadIdx.x;
    if (t < N_EDGES) {
        int s = is64 ? (int)((const long long*)ei)[t] : ((const int*)ei)[t];
        int d = is64 ? (int)((const long long*)ei)[N_EDGES + t]
                     : ((const int*)ei)[N_EDGES + t];
        int pos = atomicAdd(&g_cursor[d], 1);
        g_cw[pos] = make_int2(s * 64, __float_as_int(g_dinv[s]));
    } else if (t < TOT) {
        int i = t - N_EDGES;
        int pos = atomicAdd(&g_cursor[i], 1);
        g_cw[pos] = make_int2(i * 64, __float_as_int(g_dinv[i]));
    }
}

// ---------------- tensor-core GEMM: M16 = [dinv *] fp16(X @ W) ----------------
template <int K, bool IN16, bool SCALE>
__global__ void __launch_bounds__(256) k_gemm(const void* __restrict__ Xv,
                                              const float* __restrict__ W,
                                              __half* __restrict__ M,
                                              int row_base) {
    constexpr int LDA = K + 8;
    constexpr int LDB = 72;
    constexpr int LDC = 72;
    constexpr int AS_BYTES = 64 * LDA * 2;
    constexpr int BS_BYTES = K * LDB * 2;
    constexpr int CS_BYTES = 64 * LDC * 4;
    constexpr int BUF = (AS_BYTES + BS_BYTES) > CS_BYTES ? (AS_BYTES + BS_BYTES) : CS_BYTES;
    __shared__ __align__(16) char buf[BUF];
    __half* As = (__half*)buf;
    __half* Bs = (__half*)(buf + AS_BYTES);
    float*  Cs = (float*)buf;

    int tid = threadIdx.x;
    int block_row = row_base + blockIdx.x * 64;

    if (IN16) {
        const __half* X16 = (const __half*)Xv;
        for (int idx = tid; idx < 64 * K / 8; idx += 256) {
            int r  = idx / (K / 8);
            int c8 = (idx % (K / 8)) * 8;
            int gr = block_row + r;
            uint4 v = (gr < N_NODES) ? *(const uint4*)&X16[(size_t)gr * K + c8]
                                     : make_uint4(0u, 0u, 0u, 0u);
            *(uint4*)&As[r * LDA + c8] = v;
        }
    } else {
        const float* X = (const float*)Xv;
        for (int idx = tid; idx < 64 * K / 4; idx += 256) {
            int r  = idx / (K / 4);
            int c4 = (idx % (K / 4)) * 4;
            int gr = block_row + r;
            float4 v = (gr < N_NODES) ? *(const float4*)&X[(size_t)gr * K + c4]
                                      : make_float4(0.f, 0.f, 0.f, 0.f);
            *(__half2*)&As[r * LDA + c4]     = __floats2half2_rn(v.x, v.y);
            *(__half2*)&As[r * LDA + c4 + 2] = __floats2half2_rn(v.z, v.w);
        }
    }
    for (int idx = tid; idx < K * 16; idx += 256) {
        int r  = idx / 16;
        int c4 = (idx % 16) * 4;
        float4 v = *(const float4*)&W[r * 64 + c4];
        *(__half2*)&Bs[r * LDB + c4]     = __floats2half2_rn(v.x, v.y);
        *(__half2*)&Bs[r * LDB + c4 + 2] = __floats2half2_rn(v.z, v.w);
    }
    __syncthreads();

    int warp = tid >> 5;
    int wc = warp & 3;
    int wr = warp >> 2;

    fragment<accumulator, 16, 16, 16, float> acc0, acc1;
    fill_fragment(acc0, 0.f);
    fill_fragment(acc1, 0.f);
    fragment<matrix_a, 16, 16, 16, __half, row_major> fa;
    fragment<matrix_b, 16, 16, 16, __half, row_major> fb;

    #pragma unroll
    for (int k0 = 0; k0 < K; k0 += 16) {
        load_matrix_sync(fb, &Bs[k0 * LDB + wc * 16], LDB);
        load_matrix_sync(fa, &As[(wr * 32) * LDA + k0], LDA);
        mma_sync(acc0, fa, fb, acc0);
        load_matrix_sync(fa, &As[(wr * 32 + 16) * LDA + k0], LDA);
        mma_sync(acc1, fa, fb, acc1);
    }
    __syncthreads();

    store_matrix_sync(&Cs[(wr * 32) * LDC + wc * 16],      acc0, LDC, mem_row_major);
    store_matrix_sync(&Cs[(wr * 32 + 16) * LDC + wc * 16], acc1, LDC, mem_row_major);
    __syncthreads();

    for (int idx = tid; idx < 64 * 8; idx += 256) {
        int r  = idx >> 3;
        int c8 = (idx & 7) * 8;
        int gr = block_row + r;
        if (gr < N_NODES) {
            float di = SCALE ? g_dinv[gr] : 1.f;
            const float* cp = &Cs[r * LDC + c8];
            __half2 h[4];
            #pragma unroll
            for (int j = 0; j < 4; j++)
                h[j] = __floats2half2_rn(cp[2 * j] * di, cp[2 * j + 1] * di);
            uint4 pack;
            pack.x = *(unsigned*)&h[0];
            pack.y = *(unsigned*)&h[1];
            pack.z = *(unsigned*)&h[2];
            pack.w = *(unsigned*)&h[3];
            *(uint4*)&M[(size_t)gr * 64 + c8] = pack;
        }
    }
}

// ---------------- half-warp fp16 aggregate (row window, 16-edge main loop) ----
template <bool WEIGHTED, bool RELU, bool OUT16, bool ADDRES>
__global__ void __launch_bounds__(512) k_agg(const __half* __restrict__ M,
                                             const float* __restrict__ bias,
                                             const __half* __restrict__ res16,
                                             void* __restrict__ outp,
                                             int row_base, int row_count) {
    int lane = threadIdx.x & 31;
    int hid  = lane >> 4;
    int hl4  = (lane & 15) * 4;
    int r    = (blockIdx.x * 512 + threadIdx.x) >> 5;
    if (r >= row_count) return;
    int row = row_base + r;

    int s  = g_rowptr[row];
    int en = g_rowptr[row + 1];
    float a0 = 0.f, a1 = 0.f, a2 = 0.f, a3 = 0.f;
    int e = s;
    // 16-edge batches: 8 independent cw->M chains per half-warp in flight
    #pragma unroll 1
    for (; e + 16 <= en; e += 16) {
        int2 cw[8];
        #pragma unroll
        for (int j = 0; j < 8; j++) cw[j] = g_cw[e + 2 * j + hid];
        #pragma unroll
        for (int j = 0; j < 8; j++) {
            uint2 hv = *(const uint2*)&M[cw[j].x + hl4];
            float2 lo = __half22float2(*(__half2*)&hv.x);
            float2 hi = __half22float2(*(__half2*)&hv.y);
            if (WEIGHTED) {
                float w = __int_as_float(cw[j].y);
                a0 = fmaf(lo.x, w, a0); a1 = fmaf(lo.y, w, a1);
                a2 = fmaf(hi.x, w, a2); a3 = fmaf(hi.y, w, a3);
            } else {
                a0 += lo.x; a1 += lo.y; a2 += hi.x; a3 += hi.y;
            }
        }
    }
    #pragma unroll 1
    for (; e + 8 <= en; e += 8) {
        #pragma unroll
        for (int j = 0; j < 4; j++) {
            int2 cw = g_cw[e + 2 * j + hid];
            uint2 hv = *(const uint2*)&M[cw.x + hl4];
            float2 lo = __half22float2(*(__half2*)&hv.x);
            float2 hi = __half22float2(*(__half2*)&hv.y);
            if (WEIGHTED) {
                float w = __int_as_float(cw.y);
                a0 = fmaf(lo.x, w, a0); a1 = fmaf(lo.y, w, a1);
                a2 = fmaf(hi.x, w, a2); a3 = fmaf(hi.y, w, a3);
            } else {
                a0 += lo.x; a1 += lo.y; a2 += hi.x; a3 += hi.y;
            }
        }
    }
    for (; e + 2 <= en; e += 2) {
        int2 cw = g_cw[e + hid];
        uint2 hv = *(const uint2*)&M[cw.x + hl4];
        float2 lo = __half22float2(*(__half2*)&hv.x);
        float2 hi = __half22float2(*(__half2*)&hv.y);
        float w = WEIGHTED ? __int_as_float(cw.y) : 1.f;
        a0 = fmaf(lo.x, w, a0); a1 = fmaf(lo.y, w, a1);
        a2 = fmaf(hi.x, w, a2); a3 = fmaf(hi.y, w, a3);
    }
    if (e < en && hid == 0) {
        int2 cw = g_cw[e];
        uint2 hv = *(const uint2*)&M[cw.x + hl4];
        float2 lo = __half22float2(*(__half2*)&hv.x);
        float2 hi = __half22float2(*(__half2*)&hv.y);
        float w = WEIGHTED ? __int_as_float(cw.y) : 1.f;
        a0 = fmaf(lo.x, w, a0); a1 = fmaf(lo.y, w, a1);
        a2 = fmaf(hi.x, w, a2); a3 = fmaf(hi.y, w, a3);
    }
    a0 += __shfl_xor_sync(0xffffffffu, a0, 16);
    a1 += __shfl_xor_sync(0xffffffffu, a1, 16);
    a2 += __shfl_xor_sync(0xffffffffu, a2, 16);
    a3 += __shfl_xor_sync(0xffffffffu, a3, 16);

    if (hid == 0) {
        float di = g_dinv[row];
        float4 b = *(const float4*)&bias[hl4];
        float o0 = fmaf(a0, di, b.x);
        float o1 = fmaf(a1, di, b.y);
        float o2 = fmaf(a2, di, b.z);
        float o3 = fmaf(a3, di, b.w);
        if (RELU) {
            o0 = fmaxf(o0, 0.f); o1 = fmaxf(o1, 0.f);
            o2 = fmaxf(o2, 0.f); o3 = fmaxf(o3, 0.f);
        }
        if (ADDRES) {
            uint2 rv = *(const uint2*)&res16[(size_t)row * 64 + hl4];
            float2 rlo = __half22float2(*(__half2*)&rv.x);
            float2 rhi = __half22float2(*(__half2*)&rv.y);
            o0 += rlo.x; o1 += rlo.y; o2 += rhi.x; o3 += rhi.y;
        }
        if (OUT16) {
            __half2 p0 = __floats2half2_rn(o0, o1);
            __half2 p1 = __floats2half2_rn(o2, o3);
            *(uint2*)&((__half*)outp)[(size_t)row * 64 + hl4] =
                make_uint2(*(unsigned*)&p0, *(unsigned*)&p1);
        } else {
            *(float4*)&((float*)outp)[(size_t)row * 64 + hl4] =
                make_float4(o0, o1, o2, o3);
        }
    }
}

// ---------------- launch --------------------------------------------------------
extern "C" void kernel_launch(void* const* d_in, const int* in_sizes, int n_in,
                              void* d_out, int out_size) {
    const float* x  = (const float*)d_in[0];
    const void*  ei = d_in[1];
    const float* W0 = (const float*)d_in[2];
    const float* b0 = (const float*)d_in[3];
    const float* Ws = (const float*)d_in[4];
    const float* bs = (const float*)d_in[5];
    float* out = (float*)d_out;

    const float* Ws0 = Ws;
    const float* Ws1 = Ws + 64 * 64;
    const float* bs0 = bs;
    const float* bs1 = bs + 64;

    __half *MA = nullptr, *MB = nullptr, *XT16 = nullptr, *H116 = nullptr;
    cudaGetSymbolAddress((void**)&MA,   g_MA);
    cudaGetSymbolAddress((void**)&MB,   g_MB);
    cudaGetSymbolAddress((void**)&XT16, g_XT16);
    cudaGetSymbolAddress((void**)&H116, g_H116);

    static cudaStream_t s2 = nullptr;
    static cudaEvent_t evF, evG0, evA0, evA1, evG1, evB0, evB1, evG2;
    if (s2 == nullptr) {
        cudaStreamCreateWithFlags(&s2, cudaStreamNonBlocking);
        cudaEventCreateWithFlags(&evF,  cudaEventDisableTiming);
        cudaEventCreateWithFlags(&evG0, cudaEventDisableTiming);
        cudaEventCreateWithFlags(&evA0, cudaEventDisableTiming);
        cudaEventCreateWithFlags(&evA1, cudaEventDisableTiming);
        cudaEventCreateWithFlags(&evG1, cudaEventDisableTiming);
        cudaEventCreateWithFlags(&evB0, cudaEventDisableTiming);
        cudaEventCreateWithFlags(&evB1, cudaEventDisableTiming);
        cudaEventCreateWithFlags(&evG2, cudaEventDisableTiming);
    }

    const int GB_ALL = (N_NODES + 63) / 64;   // 1563
    const int GB_H0  = NHALF / 64;            // 781
    const int GB_H1  = (NREST + 63) / 64;     // 782
    const int AB_H0  = (NHALF * 32) / 512;    // 3124
    const int AB_H1  = (NREST * 32) / 512;    // 3126
    const int AB_ALL = (N_NODES * 32 + 511) / 512;

    // ---- fork: gemm0 on side stream, CSR build on default ----
    cudaEventRecord(evF, 0);
    cudaStreamWaitEvent(s2, evF, 0);
    k_gemm<128, false, false><<<GB_ALL, 256, 0, s2>>>(x, W0, MA, 0);
    cudaEventRecord(evG0, s2);

    k_count<<<(N_EDGES + 511) / 512, 512>>>(ei);
    k_scan1<<<NB_SCAN, 1024>>>();
    k_scan2f<<<NB_SCAN, 1024>>>();
    k_fill<<<(TOT + 511) / 512, 512>>>(ei);

    cudaStreamWaitEvent(0, evG0, 0);

    // ---- layer 0: agg (weighted) in halves -> XT16; gemm1 halves overlap on s2
    k_agg<true, false, true, false><<<AB_H0, 512>>>(MA, b0, nullptr, XT16, 0, NHALF);
    cudaEventRecord(evA0, 0);
    k_agg<true, false, true, false><<<AB_H1, 512>>>(MA, b0, nullptr, XT16, NHALF, NREST);
    cudaEventRecord(evA1, 0);

    cudaStreamWaitEvent(s2, evA0, 0);
    k_gemm<64, true, true><<<GB_H0, 256, 0, s2>>>(XT16, Ws0, MB, 0);
    cudaStreamWaitEvent(s2, evA1, 0);
    k_gemm<64, true, true><<<GB_H1, 256, 0, s2>>>(XT16, Ws0, MB, NHALF);
    cudaEventRecord(evG1, s2);

    // ---- layer 1: agg halves -> H116; gemm2 halves overlap on s2
    cudaStreamWaitEvent(0, evG1, 0);
    k_agg<false, true, true, false><<<AB_H0, 512>>>(MB, bs0, nullptr, H116, 0, NHALF);
    cudaEventRecord(evB0, 0);
    k_agg<false, true, true, false><<<AB_H1, 512>>>(MB, bs0, nullptr, H116, NHALF, NREST);
    cudaEventRecord(evB1, 0);

    cudaStreamWaitEvent(s2, evB0, 0);
    k_gemm<64, true, true><<<GB_H0, 256, 0, s2>>>(H116, Ws1, MA, 0);
    cudaStreamWaitEvent(s2, evB1, 0);
    k_gemm<64, true, true><<<GB_H1, 256, 0, s2>>>(H116, Ws1, MA, NHALF);
    cudaEventRecord(evG2, s2);

    // ---- layer 2: agg + residual -> out (fp32)
    cudaStreamWaitEvent(0, evG2, 0);
    k_agg<false, true, false, true><<<AB_ALL, 512>>>(MA, bs1, XT16, out, 0, N_NODES);
}